// round 14
// baseline (speedup 1.0000x reference)
#include <cuda_runtime.h>
#include <cuda_bf16.h>
#include <cuda_fp16.h>
#include <cstdint>

// Problem constants (fixed by the dataset)
#define BB   8
#define LQ   5440
#define LIN  5440
#define DM   256
#define NH   8
#define MTOT (BB * LQ)   // 43520

// ---------------------------------------------------------------------------
// Scratch (device globals; allocation-free per harness rules)
// ---------------------------------------------------------------------------
// value per-head layout: [8 heads][MTOT+2 rows][32 ch] fp16, +1 pad row each
// side (data starts at row 1). 64B per row -> x-corner pairs share 128B.
#define VROWS (MTOT + 2)
__device__ __align__(16) __half g_v[NH * VROWS * 32];
__device__ __align__(16) float  g_oa  [MTOT * 384];         // off(256) + attn logits(128)
// fp16 activations in chunk-contiguous GEMM layout:
// half index = ((k>>6)*MTOT + row)*64 + (k&63)
__device__ __align__(16) __half g_core_h[MTOT * DM];
__device__ __align__(16) __half g_if_h  [MTOT * DM];        // inpf fp16
__device__ __align__(16) __half g_q_h   [MTOT * DM];        // query fp16

// Pre-transposed fp16 weights, chunk-contiguous layout:
// element index = ((k>>6)*N + n)*64 + (k&63)   (64-wide K chunks)
__device__ __align__(16) __half g_wv [DM * DM];
__device__ __align__(16) __half g_woa[DM * 384];
__device__ __align__(16) __half g_wu [DM * DM];
__device__ __align__(16) float g_boa[384];

// ---------------------------------------------------------------------------
// Helpers
// ---------------------------------------------------------------------------
__device__ __forceinline__ uint32_t smem_u32(const void* p) {
    uint32_t a;
    asm("{ .reg .u64 t; cvta.to.shared.u64 t, %1; cvt.u32.u64 %0, t; }"
        : "=r"(a) : "l"(p));
    return a;
}
__device__ __forceinline__ void ldsm4(uint32_t* d, uint32_t addr) {
    asm volatile("ldmatrix.sync.aligned.m8n8.x4.shared.b16 {%0,%1,%2,%3}, [%4];"
                 : "=r"(d[0]), "=r"(d[1]), "=r"(d[2]), "=r"(d[3]) : "r"(addr));
}
__device__ __forceinline__ void mma16816(float* c, const uint32_t* a,
                                         const uint32_t* b) {
    asm volatile(
        "mma.sync.aligned.m16n8k16.row.col.f32.f16.f16.f32 "
        "{%0,%1,%2,%3}, {%4,%5,%6,%7}, {%8,%9}, {%0,%1,%2,%3};"
        : "+f"(c[0]), "+f"(c[1]), "+f"(c[2]), "+f"(c[3])
        : "r"(a[0]), "r"(a[1]), "r"(a[2]), "r"(a[3]), "r"(b[0]), "r"(b[1]));
}
__device__ __forceinline__ void cp16(uint32_t dst, const void* src) {
    asm volatile("cp.async.cg.shared.global [%0], [%1], 16;"
                 :: "r"(dst), "l"(src) : "memory");
}

// ---------------------------------------------------------------------------
// Weight prep (transpose + fp16, chunk layout) + combined bias
// ---------------------------------------------------------------------------
__global__ void prep_all(const float* __restrict__ W_val,
                         const float* __restrict__ W_off,
                         const float* __restrict__ W_attn,
                         const float* __restrict__ W_out,
                         const float* __restrict__ b_off,
                         const float* __restrict__ b_attn)
{
    int idx = blockIdx.x * 256 + threadIdx.x;
    if (idx < 384)
        g_boa[idx] = idx < 256 ? b_off[idx] : b_attn[idx - 256];

    float v; __half* w; int o;
    if (idx < 65536) {                       // W_val [256x256]
        int k = idx >> 8, n = idx & 255;
        v = W_val[idx];
        o = (((k >> 6) << 8) + n) * 64 + (k & 63);
        w = g_wv;
    } else if (idx < 65536 + 98304) {        // combined [256x384]
        int t = idx - 65536;
        int k = t / 384, n = t - k * 384;
        v = n < 256 ? W_off[k * 256 + n] : W_attn[k * 128 + (n - 256)];
        o = ((k >> 6) * 384 + n) * 64 + (k & 63);
        w = g_woa;
    } else {                                 // W_out [256x256]
        int t = idx - 65536 - 98304;
        int k = t >> 8, n = t & 255;
        v = W_out[t];
        o = (((k >> 6) << 8) + n) * 64 + (k & 63);
        w = g_wu;
    }
    w[o] = __float2half_rn(v);
}

// ---------------------------------------------------------------------------
// Activation convert: inpf + query fp32 -> fp16 chunk-contiguous layout.
// ---------------------------------------------------------------------------
__global__ __launch_bounds__(256) void convert_act(
    const float* __restrict__ inpf, const float* __restrict__ query)
{
    const int t  = blockIdx.x * 256 + threadIdx.x;
    const int u  = t & 7;
    const int q  = t >> 3;
    const int row = q % MTOT;
    const int cc  = q / MTOT;          // 0..7
    const int c   = cc & 3;
    const float* src = (cc < 4) ? inpf : query;
    __half* dst      = (cc < 4) ? g_if_h : g_q_h;

    const float4* sp = (const float4*)(src + (size_t)row * 256 + c * 64 + u * 8);
    float4 v0 = sp[0], v1 = sp[1];
    __half2 h[4];
    h[0] = __floats2half2_rn(v0.x, v0.y);
    h[1] = __floats2half2_rn(v0.z, v0.w);
    h[2] = __floats2half2_rn(v1.x, v1.y);
    h[3] = __floats2half2_rn(v1.z, v1.w);
    *(uint4*)(dst + ((size_t)c * MTOT + row) * 64 + u * 8) = *(uint4*)h;
}

// ---------------------------------------------------------------------------
// Fused val+oa GEMM, 3-stage cp.async pipeline, one sync per chunk.
// grid (5, 340): bx<2 -> value GEMM (A=g_if_h, B=g_wv, N=256 -> g_v per-head);
//                bx>=2 -> off+attn GEMM (A=g_q_h, B=g_woa, N=384 -> g_oa fp32).
// ---------------------------------------------------------------------------
__global__ __launch_bounds__(256, 2) void gemm_dual(
    const float* __restrict__ b_val)
{
    extern __shared__ char smem[];
    constexpr int BUF = 32768, O_B = 16384;

    const int tid  = threadIdx.x;
    const int wid  = tid >> 5;
    const int lane = tid & 31;
    const int mBase = blockIdx.y * 128;
    const bool isVal = blockIdx.x < 2;
    const int N     = isVal ? 256 : 384;
    const int nBase = (isVal ? blockIdx.x : blockIdx.x - 2) * 128;
    const int warpM = (wid & 3) * 32;
    const int warpN = (wid >> 2) * 64;

    const uint4* Ag = (const uint4*)(isVal ? g_if_h : g_q_h);
    const uint4* Bg = (const uint4*)(isVal ? g_wv  : g_woa);
    const float* bias = isVal ? b_val : g_boa;

    float acc[2][8][4];
#pragma unroll
    for (int i = 0; i < 2; i++)
#pragma unroll
        for (int j = 0; j < 8; j++)
#pragma unroll
            for (int k = 0; k < 4; k++) acc[i][j][k] = 0.f;

    auto loadChunk = [&](int c, int s) {
        uint32_t as = smem_u32(smem + s * BUF);
        uint32_t bs = as + O_B;
#pragma unroll
        for (int i = 0; i < 4; i++) {           // A: 1024 uint4
            int f = tid + 256 * i;
            int row = f >> 3, u = f & 7;
            uint32_t so = (row << 7) + (((u ^ (row & 7))) << 4);
            size_t gi = (size_t)(c * MTOT + mBase + row) * 8 + u;
            cp16(as + so, Ag + gi);
        }
#pragma unroll
        for (int i = 0; i < 4; i++) {           // B: 1024 uint4
            int f = tid + 256 * i;
            int n = f >> 3, u = f & 7;
            uint32_t so = (n << 7) + (((u ^ (n & 7))) << 4);
            size_t gi = (size_t)(c * N + nBase + n) * 8 + u;
            cp16(bs + so, Bg + gi);
        }
        asm volatile("cp.async.commit_group;" ::: "memory");
    };

    loadChunk(0, 0);
    loadChunk(1, 1);

    for (int c = 0; c < 4; c++) {
        if (c < 3) asm volatile("cp.async.wait_group 1;" ::: "memory");
        else       asm volatile("cp.async.wait_group 0;" ::: "memory");
        __syncthreads();
        if (c < 2) loadChunk(c + 2, (c + 2) % 3);

        const uint32_t As = smem_u32(smem + (c % 3) * BUF);
        const uint32_t Bs = As + O_B;

#pragma unroll
        for (int kk = 0; kk < 4; kk++) {
            uint32_t ah[2][4];
#pragma unroll
            for (int mi = 0; mi < 2; mi++) {
                int r = warpM + mi * 16 + (lane & 15);
                int u = kk * 2 + (lane >> 4);
                uint32_t off = (r << 7) + (((u ^ (r & 7))) << 4);
                ldsm4(ah[mi], As + off);
            }
            uint32_t bh[8][2];
#pragma unroll
            for (int p = 0; p < 4; p++) {
                int r = warpN + p * 16 + ((lane >> 4) << 3) + (lane & 7);
                int u = kk * 2 + ((lane >> 3) & 1);
                uint32_t off = (r << 7) + (((u ^ (r & 7))) << 4);
                ldsm4(&bh[p * 2][0], Bs + off);
            }
#pragma unroll
            for (int mi = 0; mi < 2; mi++)
#pragma unroll
                for (int nj = 0; nj < 8; nj++)
                    mma16816(acc[mi][nj], ah[mi], bh[nj]);
        }
        if (c < 3) __syncthreads();
    }

#pragma unroll
    for (int mi = 0; mi < 2; mi++) {
        int row0 = mBase + warpM + mi * 16 + (lane >> 2);
#pragma unroll
        for (int nj = 0; nj < 8; nj++) {
            int col = nBase + warpN + nj * 8 + (lane & 3) * 2;
            float bx = __ldg(bias + col), by = __ldg(bias + col + 1);
            float v00 = acc[mi][nj][0] + bx, v01 = acc[mi][nj][1] + by;
            float v10 = acc[mi][nj][2] + bx, v11 = acc[mi][nj][3] + by;
            if (isVal) {
                // per-head layout: h = col>>5, ch = col&31, +1 pad row
                int h = col >> 5, ch = col & 31;
                __half* vb = g_v + (size_t)h * VROWS * 32 + 32 + ch;
                *(__half2*)(vb + (size_t)row0 * 32)       = __floats2half2_rn(v00, v01);
                *(__half2*)(vb + (size_t)(row0 + 8) * 32) = __floats2half2_rn(v10, v11);
            } else {
                *(float2*)(g_oa + (size_t)row0 * 384 + col)       = make_float2(v00, v01);
                *(float2*)(g_oa + (size_t)(row0 + 8) * 384 + col) = make_float2(v10, v11);
            }
        }
    }
}

// ---------------------------------------------------------------------------
// Output GEMM (N=256, A=g_core_h fp16 chunk layout), 3-stage pipeline.
// ---------------------------------------------------------------------------
__global__ __launch_bounds__(256, 2) void gemm_out(
    const float* __restrict__ bias, float* __restrict__ C)
{
    extern __shared__ char smem[];
    constexpr int BUF = 32768, O_B = 16384;
    constexpr int N = 256;

    const int tid  = threadIdx.x;
    const int wid  = tid >> 5;
    const int lane = tid & 31;
    const int mBase = blockIdx.y * 128;
    const int nBase = blockIdx.x * 128;
    const int warpM = (wid & 3) * 32;
    const int warpN = (wid >> 2) * 64;

    const uint4* Ag = (const uint4*)g_core_h;
    const uint4* Bg = (const uint4*)g_wu;

    float acc[2][8][4];
#pragma unroll
    for (int i = 0; i < 2; i++)
#pragma unroll
        for (int j = 0; j < 8; j++)
#pragma unroll
            for (int k = 0; k < 4; k++) acc[i][j][k] = 0.f;

    auto loadChunk = [&](int c, int s) {
        uint32_t as = smem_u32(smem + s * BUF);
        uint32_t bs = as + O_B;
#pragma unroll
        for (int i = 0; i < 4; i++) {
            int f = tid + 256 * i;
            int row = f >> 3, u = f & 7;
            uint32_t so = (row << 7) + (((u ^ (row & 7))) << 4);
            size_t gi = (size_t)(c * MTOT + mBase + row) * 8 + u;
            cp16(as + so, Ag + gi);
        }
#pragma unroll
        for (int i = 0; i < 4; i++) {
            int f = tid + 256 * i;
            int n = f >> 3, u = f & 7;
            uint32_t so = (n << 7) + (((u ^ (n & 7))) << 4);
            size_t gi = (size_t)(c * N + nBase + n) * 8 + u;
            cp16(bs + so, Bg + gi);
        }
        asm volatile("cp.async.commit_group;" ::: "memory");
    };

    loadChunk(0, 0);
    loadChunk(1, 1);

    for (int c = 0; c < 4; c++) {
        if (c < 3) asm volatile("cp.async.wait_group 1;" ::: "memory");
        else       asm volatile("cp.async.wait_group 0;" ::: "memory");
        __syncthreads();
        if (c < 2) loadChunk(c + 2, (c + 2) % 3);

        const uint32_t As = smem_u32(smem + (c % 3) * BUF);
        const uint32_t Bs = As + O_B;

#pragma unroll
        for (int kk = 0; kk < 4; kk++) {
            uint32_t ah[2][4];
#pragma unroll
            for (int mi = 0; mi < 2; mi++) {
                int r = warpM + mi * 16 + (lane & 15);
                int u = kk * 2 + (lane >> 4);
                uint32_t off = (r << 7) + (((u ^ (r & 7))) << 4);
                ldsm4(ah[mi], As + off);
            }
            uint32_t bh[8][2];
#pragma unroll
            for (int p = 0; p < 4; p++) {
                int r = warpN + p * 16 + ((lane >> 4) << 3) + (lane & 7);
                int u = kk * 2 + ((lane >> 3) & 1);
                uint32_t off = (r << 7) + (((u ^ (r & 7))) << 4);
                ldsm4(&bh[p * 2][0], Bs + off);
            }
#pragma unroll
            for (int mi = 0; mi < 2; mi++)
#pragma unroll
                for (int nj = 0; nj < 8; nj++)
                    mma16816(acc[mi][nj], ah[mi], bh[nj]);
        }
        if (c < 3) __syncthreads();
    }

#pragma unroll
    for (int mi = 0; mi < 2; mi++) {
        int row0 = mBase + warpM + mi * 16 + (lane >> 2);
#pragma unroll
        for (int nj = 0; nj < 8; nj++) {
            int col = nBase + warpN + nj * 8 + (lane & 3) * 2;
            float bx = __ldg(bias + col), by = __ldg(bias + col + 1);
            *(float2*)(C + (size_t)row0 * N + col) =
                make_float2(acc[mi][nj][0] + bx, acc[mi][nj][1] + by);
            *(float2*)(C + (size_t)(row0 + 8) * N + col) =
                make_float2(acc[mi][nj][2] + bx, acc[mi][nj][3] + by);
        }
    }
}

// ---------------------------------------------------------------------------
// Fused softmax + deformable sampling, per-head 64B-row value layout.
// Block = 256 threads = 2 query rows x 8 heads = 16 slots.
// Phase 1: per (slot, point): compute softmax'd weights + row indices with
//   cx = clamp(x0,-1,W-1); entry[xh] = {r_y0+xh, r_y1+xh, w_y0, w_y1}.
// Phase 2: warp = 2 slots; slot group = 16 lanes = 2 x-halves x 8 lanes
//   (4 channels each, LDG.64). Both x-corners of a y-row land in one
//   contiguous 128B region. One LDS.128 (64B/warp contiguous) per point.
//   x-half combine via shfl_xor(8).
// ---------------------------------------------------------------------------
__global__ __launch_bounds__(256) void msda_sample(const float* __restrict__ refp)
{
    __shared__ int4 tab[16][32];   // [point][slot*2+xh]

    const int tid = threadIdx.x;
    const int rowBase = blockIdx.x * 2;

    // ---- Phase 1: per-(slot, point) setup ----
    {
        const int hs  = tid >> 4;        // slot 0..15
        const int s   = tid & 15;        // point (lvl*4 + pt)
        const int row = rowBase + (hs >> 3);
        const int h   = hs & 7;
        const int b   = row / LQ;

        const int lvl = s >> 2;
        const int Wl  = 64 >> lvl;
        const int st  = (16384 - (16384 >> (2 * lvl))) / 3;

        const float refx = refp[row * 8 + lvl * 2 + 0];
        const float refy = refp[row * 8 + lvl * 2 + 1];
        const int obase  = row * 384 + ((h * 16 + s) * 2);
        const float offx = g_oa[obase + 0];
        const float offy = g_oa[obase + 1];

        const float x = refx * (float)Wl + offx - 0.5f;
        const float y = refy * (float)Wl + offy - 0.5f;
        const float fx = floorf(x), fy = floorf(y);
        const float lx = x - fx,   ly = y - fy;
        const int x0 = (int)fx, y0 = (int)fy;
        const int x1 = x0 + 1,  y1 = y0 + 1;

        const float logit = g_oa[row * 384 + 256 + h * 16 + s];
        float mx = logit;
#pragma unroll
        for (int o = 8; o; o >>= 1) mx = fmaxf(mx, __shfl_xor_sync(~0u, mx, o, 16));
        const float e = __expf(logit - mx);
        float sum = e;
#pragma unroll
        for (int o = 8; o; o >>= 1) sum += __shfl_xor_sync(~0u, sum, o, 16);
        const float wa = e / sum;

        const bool vx0 = (unsigned)x0 < (unsigned)Wl;
        const bool vx1 = (unsigned)x1 < (unsigned)Wl;
        const bool vy0 = (unsigned)y0 < (unsigned)Wl;
        const bool vy1 = (unsigned)y1 < (unsigned)Wl;
        const int cx  = min(max(x0, -1), Wl - 1);      // pair base column
        const int cy0 = min(max(y0, 0), Wl - 1);
        const int cy1 = min(max(y1, 0), Wl - 1);
        const int rb  = b * LIN + st;
        const int r0  = rb + cy0 * Wl + cx;            // may be -1 (front pad)
        const int r1  = rb + cy1 * Wl + cx;

        const float w00 = wa * (1.f - lx) * (1.f - ly) * (float)(vx0 && vy0);
        const float w01 = wa * lx         * (1.f - ly) * (float)(vx1 && vy0);
        const float w10 = wa * (1.f - lx) * ly         * (float)(vx0 && vy1);
        const float w11 = wa * lx         * ly         * (float)(vx1 && vy1);

        tab[s][hs * 2 + 0] = make_int4(r0,     r1,     __float_as_int(w00), __float_as_int(w10));
        tab[s][hs * 2 + 1] = make_int4(r0 + 1, r1 + 1, __float_as_int(w01), __float_as_int(w11));
    }
    __syncthreads();

    // ---- Phase 2: gather + accumulate ----
    const int wid  = tid >> 5;
    const int lane = tid & 31;
    const int slot = wid * 2 + (lane >> 4);
    const int row  = rowBase + (slot >> 3);
    const int h    = slot & 7;
    const int cl   = lane & 7;                 // channel quad (4 ch)
    const int eidx = wid * 4 + (lane >> 3);    // tab entry: slot*2+xh

    const __half* __restrict__ vb = g_v + (size_t)h * VROWS * 32 + 32 + cl * 4;

    float a0 = 0.f, a1 = 0.f, a2 = 0.f, a3 = 0.f;
#pragma unroll 4
    for (int t = 0; t < 16; t++) {
        const int4 e = tab[t][eidx];
        const float wA = __int_as_float(e.z);
        const float wB = __int_as_float(e.w);
        const uint2 v0 = *(const uint2*)(vb + (size_t)e.x * 32);
        const uint2 v1 = *(const uint2*)(vb + (size_t)e.y * 32);
        const float2 p0 = __half22float2(*(const __half2*)&v0.x);
        const float2 p1 = __half22float2(*(const __half2*)&v0.y);
        const float2 q0 = __half22float2(*(const __half2*)&v1.x);
        const float2 q1 = __half22float2(*(const __half2*)&v1.y);
        a0 += wA * p0.x + wB * q0.x;
        a1 += wA * p0.y + wB * q0.y;
        a2 += wA * p1.x + wB * q1.x;
        a3 += wA * p1.y + wB * q1.y;
    }
    // combine x-halves (lanes L and L+8 hold complementary corners)
    a0 += __shfl_xor_sync(~0u, a0, 8);
    a1 += __shfl_xor_sync(~0u, a1, 8);
    a2 += __shfl_xor_sync(~0u, a2, 8);
    a3 += __shfl_xor_sync(~0u, a3, 8);

    if (((lane >> 3) & 1) == 0) {
        __half2 o0 = __floats2half2_rn(a0, a1);
        __half2 o1 = __floats2half2_rn(a2, a3);
        size_t o = ((size_t)(h >> 1) * MTOT + row) * 64 + (h & 1) * 32 + cl * 4;
        *(__half2*)(g_core_h + o)     = o0;
        *(__half2*)(g_core_h + o + 2) = o1;
    }
}

// ---------------------------------------------------------------------------
extern "C" void kernel_launch(void* const* d_in, const int* in_sizes, int n_in,
                              void* d_out, int out_size)
{
    const float* query  = (const float*)d_in[0];
    const float* refp   = (const float*)d_in[1];
    const float* inpf   = (const float*)d_in[2];
    const float* W_val  = (const float*)d_in[5];
    const float* b_val  = (const float*)d_in[6];
    const float* W_off  = (const float*)d_in[7];
    const float* b_off  = (const float*)d_in[8];
    const float* W_attn = (const float*)d_in[9];
    const float* b_attn = (const float*)d_in[10];
    const float* W_out  = (const float*)d_in[11];
    const float* b_out  = (const float*)d_in[12];
    float* out = (float*)d_out;

    constexpr int SMEM = 98304;   // 3 x 32KB
    cudaFuncSetAttribute(gemm_dual, cudaFuncAttributeMaxDynamicSharedMemorySize, SMEM);
    cudaFuncSetAttribute(gemm_out,  cudaFuncAttributeMaxDynamicSharedMemorySize, SMEM);

    prep_all<<<896, 256>>>(W_val, W_off, W_attn, W_out, b_off, b_attn);
    convert_act<<<10880, 256>>>(inpf, query);

    const int MT = MTOT / 128;  // 340
    gemm_dual<<<dim3(5, MT), 256, SMEM>>>(b_val);

    msda_sample<<<MTOT / 2, 256>>>(refp);

    gemm_out<<<dim3(2, MT), 256, SMEM>>>(b_out, out);
}

// round 15
// speedup vs baseline: 1.0012x; 1.0012x over previous
#include <cuda_runtime.h>
#include <cuda_bf16.h>
#include <cuda_fp16.h>
#include <cstdint>

// Problem constants (fixed by the dataset)
#define BB   8
#define LQ   5440
#define LIN  5440
#define DM   256
#define NH   8
#define MTOT (BB * LQ)   // 43520

// ---------------------------------------------------------------------------
// Scratch (device globals; allocation-free per harness rules)
// ---------------------------------------------------------------------------
__device__ __align__(16) __half g_value_h[MTOT * DM];       // fp16 value
__device__ __align__(16) float  g_oa  [MTOT * 384];         // off(256) + attn logits(128)
// fp16 activations in chunk-contiguous GEMM layout:
// half index = ((k>>6)*MTOT + row)*64 + (k&63)
__device__ __align__(16) __half g_core_h[MTOT * DM];
__device__ __align__(16) __half g_if_h  [MTOT * DM];        // inpf fp16
__device__ __align__(16) __half g_q_h   [MTOT * DM];        // query fp16

// Pre-transposed fp16 weights, chunk-contiguous layout:
// element index = ((k>>6)*N + n)*64 + (k&63)   (64-wide K chunks)
__device__ __align__(16) __half g_wv [DM * DM];
__device__ __align__(16) __half g_woa[DM * 384];
__device__ __align__(16) __half g_wu [DM * DM];
__device__ __align__(16) float g_boa[384];

// ---------------------------------------------------------------------------
// Helpers
// ---------------------------------------------------------------------------
__device__ __forceinline__ uint32_t smem_u32(const void* p) {
    uint32_t a;
    asm("{ .reg .u64 t; cvta.to.shared.u64 t, %1; cvt.u32.u64 %0, t; }"
        : "=r"(a) : "l"(p));
    return a;
}
__device__ __forceinline__ void ldsm4(uint32_t* d, uint32_t addr) {
    asm volatile("ldmatrix.sync.aligned.m8n8.x4.shared.b16 {%0,%1,%2,%3}, [%4];"
                 : "=r"(d[0]), "=r"(d[1]), "=r"(d[2]), "=r"(d[3]) : "r"(addr));
}
__device__ __forceinline__ void mma16816(float* c, const uint32_t* a,
                                         const uint32_t* b) {
    asm volatile(
        "mma.sync.aligned.m16n8k16.row.col.f32.f16.f16.f32 "
        "{%0,%1,%2,%3}, {%4,%5,%6,%7}, {%8,%9}, {%0,%1,%2,%3};"
        : "+f"(c[0]), "+f"(c[1]), "+f"(c[2]), "+f"(c[3])
        : "r"(a[0]), "r"(a[1]), "r"(a[2]), "r"(a[3]), "r"(b[0]), "r"(b[1]));
}
__device__ __forceinline__ void cp16(uint32_t dst, const void* src) {
    asm volatile("cp.async.cg.shared.global [%0], [%1], 16;"
                 :: "r"(dst), "l"(src) : "memory");
}

// ---------------------------------------------------------------------------
// Merged prep: blocks [0,896) = weight transpose/convert + bias;
//              blocks [896, 896+10880) = activation fp32->fp16 chunk layout.
// ---------------------------------------------------------------------------
__global__ __launch_bounds__(256) void prep_convert(
    const float* __restrict__ W_val,
    const float* __restrict__ W_off,
    const float* __restrict__ W_attn,
    const float* __restrict__ W_out,
    const float* __restrict__ b_off,
    const float* __restrict__ b_attn,
    const float* __restrict__ inpf,
    const float* __restrict__ query)
{
    if (blockIdx.x < 896) {
        int idx = blockIdx.x * 256 + threadIdx.x;
        if (idx < 384)
            g_boa[idx] = idx < 256 ? b_off[idx] : b_attn[idx - 256];

        float v; __half* w; int o;
        if (idx < 65536) {                       // W_val [256x256]
            int k = idx >> 8, n = idx & 255;
            v = W_val[idx];
            o = (((k >> 6) << 8) + n) * 64 + (k & 63);
            w = g_wv;
        } else if (idx < 65536 + 98304) {        // combined [256x384]
            int t = idx - 65536;
            int k = t / 384, n = t - k * 384;
            v = n < 256 ? W_off[k * 256 + n] : W_attn[k * 128 + (n - 256)];
            o = ((k >> 6) * 384 + n) * 64 + (k & 63);
            w = g_woa;
        } else {                                 // W_out [256x256]
            int t = idx - 65536 - 98304;
            int k = t >> 8, n = t & 255;
            v = W_out[t];
            o = (((k >> 6) << 8) + n) * 64 + (k & 63);
            w = g_wu;
        }
        w[o] = __float2half_rn(v);
    } else {
        const int t  = (blockIdx.x - 896) * 256 + threadIdx.x;
        const int u  = t & 7;
        const int q  = t >> 3;
        const int row = q % MTOT;
        const int cc  = q / MTOT;          // 0..7
        const int c   = cc & 3;
        const float* src = (cc < 4) ? inpf : query;
        __half* dst      = (cc < 4) ? g_if_h : g_q_h;

        const float4* sp = (const float4*)(src + (size_t)row * 256 + c * 64 + u * 8);
        float4 v0 = sp[0], v1 = sp[1];
        __half2 h[4];
        h[0] = __floats2half2_rn(v0.x, v0.y);
        h[1] = __floats2half2_rn(v0.z, v0.w);
        h[2] = __floats2half2_rn(v1.x, v1.y);
        h[3] = __floats2half2_rn(v1.z, v1.w);
        *(uint4*)(dst + ((size_t)c * MTOT + row) * 64 + u * 8) = *(uint4*)h;
    }
}

// ---------------------------------------------------------------------------
// Fused val+oa GEMM: CTA 128x64, 8 warps (warp tile 32x32), 3-stage cp.async
// pipeline (24KB/stage, 72KB -> 3 CTAs/SM, 24 warps).
// grid (10, 340): bx<4 -> value (A=g_if_h, B=g_wv, N=256, out fp16);
//                 bx>=4 -> off+attn (A=g_q_h, B=g_woa, N=384, out fp32).
// ---------------------------------------------------------------------------
__global__ __launch_bounds__(256, 3) void gemm_dual(
    const float* __restrict__ b_val)
{
    extern __shared__ char smem[];
    constexpr int BUF = 24576, O_B = 16384;

    const int tid  = threadIdx.x;
    const int wid  = tid >> 5;
    const int lane = tid & 31;
    const int mBase = blockIdx.y * 128;
    const bool isVal = blockIdx.x < 4;
    const int N     = isVal ? 256 : 384;
    const int nBase = (isVal ? blockIdx.x : blockIdx.x - 4) * 64;
    const int warpM = (wid & 3) * 32;
    const int warpN = (wid >> 2) * 32;

    const uint4* Ag = (const uint4*)(isVal ? g_if_h : g_q_h);
    const uint4* Bg = (const uint4*)(isVal ? g_wv  : g_woa);
    const float* bias = isVal ? b_val : g_boa;

    float acc[2][4][4];
#pragma unroll
    for (int i = 0; i < 2; i++)
#pragma unroll
        for (int j = 0; j < 4; j++)
#pragma unroll
            for (int k = 0; k < 4; k++) acc[i][j][k] = 0.f;

    auto loadChunk = [&](int c, int s) {
        uint32_t as = smem_u32(smem + s * BUF);
        uint32_t bs = as + O_B;
#pragma unroll
        for (int i = 0; i < 4; i++) {           // A: 1024 uint4
            int f = tid + 256 * i;
            int row = f >> 3, u = f & 7;
            uint32_t so = (row << 7) + (((u ^ (row & 7))) << 4);
            size_t gi = (size_t)(c * MTOT + mBase + row) * 8 + u;
            cp16(as + so, Ag + gi);
        }
#pragma unroll
        for (int i = 0; i < 2; i++) {           // B: 512 uint4
            int f = tid + 256 * i;
            int n = f >> 3, u = f & 7;
            uint32_t so = (n << 7) + (((u ^ (n & 7))) << 4);
            size_t gi = (size_t)(c * N + nBase + n) * 8 + u;
            cp16(bs + so, Bg + gi);
        }
        asm volatile("cp.async.commit_group;" ::: "memory");
    };

    loadChunk(0, 0);
    loadChunk(1, 1);

    for (int c = 0; c < 4; c++) {
        if (c < 3) asm volatile("cp.async.wait_group 1;" ::: "memory");
        else       asm volatile("cp.async.wait_group 0;" ::: "memory");
        __syncthreads();
        if (c < 2) loadChunk(c + 2, (c + 2) % 3);

        const uint32_t As = smem_u32(smem + (c % 3) * BUF);
        const uint32_t Bs = As + O_B;

#pragma unroll
        for (int kk = 0; kk < 4; kk++) {
            uint32_t ah[2][4];
#pragma unroll
            for (int mi = 0; mi < 2; mi++) {
                int r = warpM + mi * 16 + (lane & 15);
                int u = kk * 2 + (lane >> 4);
                uint32_t off = (r << 7) + (((u ^ (r & 7))) << 4);
                ldsm4(ah[mi], As + off);
            }
            uint32_t bh[4][2];
#pragma unroll
            for (int p = 0; p < 2; p++) {
                int r = warpN + p * 16 + ((lane >> 4) << 3) + (lane & 7);
                int u = kk * 2 + ((lane >> 3) & 1);
                uint32_t off = (r << 7) + (((u ^ (r & 7))) << 4);
                ldsm4(&bh[p * 2][0], Bs + off);
            }
#pragma unroll
            for (int mi = 0; mi < 2; mi++)
#pragma unroll
                for (int nj = 0; nj < 4; nj++)
                    mma16816(acc[mi][nj], ah[mi], bh[nj]);
        }
        if (c < 3) __syncthreads();
    }

#pragma unroll
    for (int mi = 0; mi < 2; mi++) {
        int row0 = mBase + warpM + mi * 16 + (lane >> 2);
#pragma unroll
        for (int nj = 0; nj < 4; nj++) {
            int col = nBase + warpN + nj * 8 + (lane & 3) * 2;
            float bx = __ldg(bias + col), by = __ldg(bias + col + 1);
            float v00 = acc[mi][nj][0] + bx, v01 = acc[mi][nj][1] + by;
            float v10 = acc[mi][nj][2] + bx, v11 = acc[mi][nj][3] + by;
            if (isVal) {
                *(__half2*)(g_value_h + (size_t)row0 * 256 + col)       = __floats2half2_rn(v00, v01);
                *(__half2*)(g_value_h + (size_t)(row0 + 8) * 256 + col) = __floats2half2_rn(v10, v11);
            } else {
                *(float2*)(g_oa + (size_t)row0 * 384 + col)       = make_float2(v00, v01);
                *(float2*)(g_oa + (size_t)(row0 + 8) * 384 + col) = make_float2(v10, v11);
            }
        }
    }
}

// ---------------------------------------------------------------------------
// Output GEMM (N=256, A=g_core_h fp16 chunk layout), same 128x64 shape.
// ---------------------------------------------------------------------------
__global__ __launch_bounds__(256, 3) void gemm_out(
    const float* __restrict__ bias, float* __restrict__ C)
{
    extern __shared__ char smem[];
    constexpr int BUF = 24576, O_B = 16384;
    constexpr int N = 256;

    const int tid  = threadIdx.x;
    const int wid  = tid >> 5;
    const int lane = tid & 31;
    const int mBase = blockIdx.y * 128;
    const int nBase = blockIdx.x * 64;
    const int warpM = (wid & 3) * 32;
    const int warpN = (wid >> 2) * 32;

    const uint4* Ag = (const uint4*)g_core_h;
    const uint4* Bg = (const uint4*)g_wu;

    float acc[2][4][4];
#pragma unroll
    for (int i = 0; i < 2; i++)
#pragma unroll
        for (int j = 0; j < 4; j++)
#pragma unroll
            for (int k = 0; k < 4; k++) acc[i][j][k] = 0.f;

    auto loadChunk = [&](int c, int s) {
        uint32_t as = smem_u32(smem + s * BUF);
        uint32_t bs = as + O_B;
#pragma unroll
        for (int i = 0; i < 4; i++) {
            int f = tid + 256 * i;
            int row = f >> 3, u = f & 7;
            uint32_t so = (row << 7) + (((u ^ (row & 7))) << 4);
            size_t gi = (size_t)(c * MTOT + mBase + row) * 8 + u;
            cp16(as + so, Ag + gi);
        }
#pragma unroll
        for (int i = 0; i < 2; i++) {
            int f = tid + 256 * i;
            int n = f >> 3, u = f & 7;
            uint32_t so = (n << 7) + (((u ^ (n & 7))) << 4);
            size_t gi = (size_t)(c * N + nBase + n) * 8 + u;
            cp16(bs + so, Bg + gi);
        }
        asm volatile("cp.async.commit_group;" ::: "memory");
    };

    loadChunk(0, 0);
    loadChunk(1, 1);

    for (int c = 0; c < 4; c++) {
        if (c < 3) asm volatile("cp.async.wait_group 1;" ::: "memory");
        else       asm volatile("cp.async.wait_group 0;" ::: "memory");
        __syncthreads();
        if (c < 2) loadChunk(c + 2, (c + 2) % 3);

        const uint32_t As = smem_u32(smem + (c % 3) * BUF);
        const uint32_t Bs = As + O_B;

#pragma unroll
        for (int kk = 0; kk < 4; kk++) {
            uint32_t ah[2][4];
#pragma unroll
            for (int mi = 0; mi < 2; mi++) {
                int r = warpM + mi * 16 + (lane & 15);
                int u = kk * 2 + (lane >> 4);
                uint32_t off = (r << 7) + (((u ^ (r & 7))) << 4);
                ldsm4(ah[mi], As + off);
            }
            uint32_t bh[4][2];
#pragma unroll
            for (int p = 0; p < 2; p++) {
                int r = warpN + p * 16 + ((lane >> 4) << 3) + (lane & 7);
                int u = kk * 2 + ((lane >> 3) & 1);
                uint32_t off = (r << 7) + (((u ^ (r & 7))) << 4);
                ldsm4(&bh[p * 2][0], Bs + off);
            }
#pragma unroll
            for (int mi = 0; mi < 2; mi++)
#pragma unroll
                for (int nj = 0; nj < 4; nj++)
                    mma16816(acc[mi][nj], ah[mi], bh[nj]);
        }
        if (c < 3) __syncthreads();
    }

#pragma unroll
    for (int mi = 0; mi < 2; mi++) {
        int row0 = mBase + warpM + mi * 16 + (lane >> 2);
#pragma unroll
        for (int nj = 0; nj < 4; nj++) {
            int col = nBase + warpN + nj * 8 + (lane & 3) * 2;
            float bx = __ldg(bias + col), by = __ldg(bias + col + 1);
            *(float2*)(C + (size_t)row0 * N + col) =
                make_float2(acc[mi][nj][0] + bx, acc[mi][nj][1] + by);
            *(float2*)(C + (size_t)(row0 + 8) * N + col) =
                make_float2(acc[mi][nj][2] + bx, acc[mi][nj][3] + by);
        }
    }
}

// ---------------------------------------------------------------------------
// Fused softmax + deformable sampling (proven R13 structure).
// Block = 256 threads = 2 query rows x 8 heads = 16 head-slots.
// Phase 2: warp serves 2 head-slots, 16 lanes per slot, lane = 2 channels
// (half2). Output written as single fp16 in the out-GEMM chunk layout.
// ---------------------------------------------------------------------------
__global__ __launch_bounds__(256) void msda_sample(const float* __restrict__ refp)
{
    __shared__ float4 sw[16][17];
    __shared__ int4   si[16][17];

    const int tid = threadIdx.x;
    const int rowBase = blockIdx.x * 2;

    // ---- Phase 1: per-(head,point) setup ----
    {
        const int hs  = tid >> 4;        // head slot 0..15
        const int s   = tid & 15;        // point (lvl*4 + pt)
        const int row = rowBase + (hs >> 3);
        const int h   = hs & 7;
        const int b   = row / LQ;

        const int lvl = s >> 2;
        const int Wl  = 64 >> lvl;
        const int st  = (16384 - (16384 >> (2 * lvl))) / 3;

        const float refx = refp[row * 8 + lvl * 2 + 0];
        const float refy = refp[row * 8 + lvl * 2 + 1];
        const int obase  = row * 384 + ((h * 16 + s) * 2);
        const float offx = g_oa[obase + 0];
        const float offy = g_oa[obase + 1];

        const float x = refx * (float)Wl + offx - 0.5f;
        const float y = refy * (float)Wl + offy - 0.5f;
        const float fx = floorf(x), fy = floorf(y);
        const float lx = x - fx,   ly = y - fy;
        const int x0 = (int)fx, y0 = (int)fy;
        const int x1 = x0 + 1,  y1 = y0 + 1;

        const float logit = g_oa[row * 384 + 256 + h * 16 + s];
        float mx = logit;
#pragma unroll
        for (int o = 8; o; o >>= 1) mx = fmaxf(mx, __shfl_xor_sync(~0u, mx, o, 16));
        const float e = __expf(logit - mx);
        float sum = e;
#pragma unroll
        for (int o = 8; o; o >>= 1) sum += __shfl_xor_sync(~0u, sum, o, 16);
        const float wa = e / sum;

        const bool vx0 = (unsigned)x0 < (unsigned)Wl;
        const bool vx1 = (unsigned)x1 < (unsigned)Wl;
        const bool vy0 = (unsigned)y0 < (unsigned)Wl;
        const bool vy1 = (unsigned)y1 < (unsigned)Wl;
        const int cx0 = min(max(x0, 0), Wl - 1);
        const int cx1 = min(max(x1, 0), Wl - 1);
        const int cy0 = min(max(y0, 0), Wl - 1);
        const int cy1 = min(max(y1, 0), Wl - 1);
        const int rb  = b * LIN + st;

        si[hs][s] = make_int4(rb + cy0 * Wl + cx0, rb + cy0 * Wl + cx1,
                              rb + cy1 * Wl + cx0, rb + cy1 * Wl + cx1);
        sw[hs][s] = make_float4(
            wa * (1.f - lx) * (1.f - ly) * (float)(vx0 && vy0),
            wa * lx         * (1.f - ly) * (float)(vx1 && vy0),
            wa * (1.f - lx) * ly         * (float)(vx0 && vy1),
            wa * lx         * ly         * (float)(vx1 && vy1));
    }
    __syncthreads();

    // ---- Phase 2: gather + accumulate ----
    const int wid  = tid >> 5;
    const int lane = tid & 31;
    const int hs   = wid * 2 + (lane >> 4);
    const int row  = rowBase + (hs >> 3);
    const int h    = hs & 7;
    const int c2   = (lane & 15) * 2;          // channel pair

    const __half* __restrict__ vp = g_value_h + h * 32 + c2;
    float ax = 0.f, ay = 0.f;
#pragma unroll 4
    for (int t = 0; t < 16; t++) {
        const float4 w  = sw[hs][t];
        const int4   id = si[hs][t];
        const float2 f0 = __half22float2(*(const __half2*)(vp + (size_t)id.x * 256));
        const float2 f1 = __half22float2(*(const __half2*)(vp + (size_t)id.y * 256));
        const float2 f2 = __half22float2(*(const __half2*)(vp + (size_t)id.z * 256));
        const float2 f3 = __half22float2(*(const __half2*)(vp + (size_t)id.w * 256));
        ax += w.x * f0.x + w.y * f1.x + w.z * f2.x + w.w * f3.x;
        ay += w.x * f0.y + w.y * f1.y + w.z * f2.y + w.w * f3.y;
    }

    // single fp16 core in out-GEMM chunk layout (k = h*32 + c2)
    size_t o = ((size_t)(h >> 1) * MTOT + row) * 64 + (h & 1) * 32 + c2;
    *(__half2*)(g_core_h + o) = __floats2half2_rn(ax, ay);
}

// ---------------------------------------------------------------------------
extern "C" void kernel_launch(void* const* d_in, const int* in_sizes, int n_in,
                              void* d_out, int out_size)
{
    const float* query  = (const float*)d_in[0];
    const float* refp   = (const float*)d_in[1];
    const float* inpf   = (const float*)d_in[2];
    const float* W_val  = (const float*)d_in[5];
    const float* b_val  = (const float*)d_in[6];
    const float* W_off  = (const float*)d_in[7];
    const float* b_off  = (const float*)d_in[8];
    const float* W_attn = (const float*)d_in[9];
    const float* b_attn = (const float*)d_in[10];
    const float* W_out  = (const float*)d_in[11];
    const float* b_out  = (const float*)d_in[12];
    float* out = (float*)d_out;

    constexpr int SMEM = 73728;   // 3 x 24KB
    cudaFuncSetAttribute(gemm_dual, cudaFuncAttributeMaxDynamicSharedMemorySize, SMEM);
    cudaFuncSetAttribute(gemm_out,  cudaFuncAttributeMaxDynamicSharedMemorySize, SMEM);

    prep_convert<<<896 + 10880, 256>>>(W_val, W_off, W_attn, W_out,
                                       b_off, b_attn, inpf, query);

    const int MT = MTOT / 128;  // 340
    gemm_dual<<<dim3(10, MT), 256, SMEM>>>(b_val);

    msda_sample<<<MTOT / 2, 256>>>(refp);

    gemm_out<<<dim3(4, MT), 256, SMEM>>>(b_out, out);
}

// round 16
// speedup vs baseline: 1.0984x; 1.0970x over previous
#include <cuda_runtime.h>
#include <cuda_bf16.h>
#include <cuda_fp16.h>
#include <cstdint>

// Problem constants (fixed by the dataset)
#define BB   8
#define LQ   5440
#define LIN  5440
#define DM   256
#define NH   8
#define MTOT (BB * LQ)   // 43520

// ---------------------------------------------------------------------------
// Scratch (device globals; allocation-free per harness rules)
// ---------------------------------------------------------------------------
__device__ __align__(16) __half g_value_h[MTOT * DM];       // fp16 value
__device__ __align__(16) float  g_oa  [MTOT * 384];         // off(256) + attn logits(128)
// fp16 activations in chunk-contiguous GEMM layout:
// half index = ((k>>6)*MTOT + row)*64 + (k&63)
__device__ __align__(16) __half g_core_h[MTOT * DM];
__device__ __align__(16) __half g_if_h  [MTOT * DM];        // inpf fp16
__device__ __align__(16) __half g_q_h   [MTOT * DM];        // query fp16

// Pre-transposed fp16 weights, chunk-contiguous layout:
// element index = ((k>>6)*N + n)*64 + (k&63)   (64-wide K chunks)
__device__ __align__(16) __half g_wv [DM * DM];
__device__ __align__(16) __half g_woa[DM * 384];
__device__ __align__(16) __half g_wu [DM * DM];
__device__ __align__(16) float g_boa[384];

// ---------------------------------------------------------------------------
// Helpers
// ---------------------------------------------------------------------------
__device__ __forceinline__ uint32_t smem_u32(const void* p) {
    uint32_t a;
    asm("{ .reg .u64 t; cvta.to.shared.u64 t, %1; cvt.u32.u64 %0, t; }"
        : "=r"(a) : "l"(p));
    return a;
}
__device__ __forceinline__ void ldsm4(uint32_t* d, uint32_t addr) {
    asm volatile("ldmatrix.sync.aligned.m8n8.x4.shared.b16 {%0,%1,%2,%3}, [%4];"
                 : "=r"(d[0]), "=r"(d[1]), "=r"(d[2]), "=r"(d[3]) : "r"(addr));
}
__device__ __forceinline__ void mma16816(float* c, const uint32_t* a,
                                         const uint32_t* b) {
    asm volatile(
        "mma.sync.aligned.m16n8k16.row.col.f32.f16.f16.f32 "
        "{%0,%1,%2,%3}, {%4,%5,%6,%7}, {%8,%9}, {%0,%1,%2,%3};"
        : "+f"(c[0]), "+f"(c[1]), "+f"(c[2]), "+f"(c[3])
        : "r"(a[0]), "r"(a[1]), "r"(a[2]), "r"(a[3]), "r"(b[0]), "r"(b[1]));
}
__device__ __forceinline__ void cp16(uint32_t dst, const void* src) {
    asm volatile("cp.async.cg.shared.global [%0], [%1], 16;"
                 :: "r"(dst), "l"(src) : "memory");
}

// ---------------------------------------------------------------------------
// Merged prep: blocks [0,896) = weight transpose/convert + bias;
//              blocks [896, 896+10880) = activation fp32->fp16 chunk layout.
// ---------------------------------------------------------------------------
__global__ __launch_bounds__(256) void prep_convert(
    const float* __restrict__ W_val,
    const float* __restrict__ W_off,
    const float* __restrict__ W_attn,
    const float* __restrict__ W_out,
    const float* __restrict__ b_off,
    const float* __restrict__ b_attn,
    const float* __restrict__ inpf,
    const float* __restrict__ query)
{
    if (blockIdx.x < 896) {
        int idx = blockIdx.x * 256 + threadIdx.x;
        if (idx < 384)
            g_boa[idx] = idx < 256 ? b_off[idx] : b_attn[idx - 256];

        float v; __half* w; int o;
        if (idx < 65536) {                       // W_val [256x256]
            int k = idx >> 8, n = idx & 255;
            v = W_val[idx];
            o = (((k >> 6) << 8) + n) * 64 + (k & 63);
            w = g_wv;
        } else if (idx < 65536 + 98304) {        // combined [256x384]
            int t = idx - 65536;
            int k = t / 384, n = t - k * 384;
            v = n < 256 ? W_off[k * 256 + n] : W_attn[k * 128 + (n - 256)];
            o = ((k >> 6) * 384 + n) * 64 + (k & 63);
            w = g_woa;
        } else {                                 // W_out [256x256]
            int t = idx - 65536 - 98304;
            int k = t >> 8, n = t & 255;
            v = W_out[t];
            o = (((k >> 6) << 8) + n) * 64 + (k & 63);
            w = g_wu;
        }
        w[o] = __float2half_rn(v);
    } else {
        const int t  = (blockIdx.x - 896) * 256 + threadIdx.x;
        const int u  = t & 7;
        const int q  = t >> 3;
        const int row = q % MTOT;
        const int cc  = q / MTOT;          // 0..7
        const int c   = cc & 3;
        const float* src = (cc < 4) ? inpf : query;
        __half* dst      = (cc < 4) ? g_if_h : g_q_h;

        const float4* sp = (const float4*)(src + (size_t)row * 256 + c * 64 + u * 8);
        float4 v0 = sp[0], v1 = sp[1];
        __half2 h[4];
        h[0] = __floats2half2_rn(v0.x, v0.y);
        h[1] = __floats2half2_rn(v0.z, v0.w);
        h[2] = __floats2half2_rn(v1.x, v1.y);
        h[3] = __floats2half2_rn(v1.z, v1.w);
        *(uint4*)(dst + ((size_t)c * MTOT + row) * 64 + u * 8) = *(uint4*)h;
    }
}

// ---------------------------------------------------------------------------
// Fused val+oa GEMM, persistent grid-stride over 1700 tiles (5 x 340).
// CTA 128x128, 8 warps (warp tile 32x64), 3-stage cp.async, 96KB (2 CTA/SM).
// bx<2 -> value GEMM (A=g_if_h, B=g_wv, N=256, out fp16);
// bx>=2 -> off+attn GEMM (A=g_q_h, B=g_woa, N=384, out fp32).
// ---------------------------------------------------------------------------
__global__ __launch_bounds__(256, 2) void gemm_dual(
    const float* __restrict__ b_val)
{
    extern __shared__ char smem[];
    constexpr int BUF = 32768, O_B = 16384;

    const int tid  = threadIdx.x;
    const int wid  = tid >> 5;
    const int lane = tid & 31;
    const int warpM = (wid & 3) * 32;
    const int warpN = (wid >> 2) * 64;

    for (int tile = blockIdx.x; tile < 5 * 340; tile += gridDim.x) {
        const int bx = tile / 340;
        const int by = tile % 340;
        const int mBase = by * 128;
        const bool isVal = bx < 2;
        const int N     = isVal ? 256 : 384;
        const int nBase = (isVal ? bx : bx - 2) * 128;

        const uint4* Ag = (const uint4*)(isVal ? g_if_h : g_q_h);
        const uint4* Bg = (const uint4*)(isVal ? g_wv  : g_woa);
        const float* bias = isVal ? b_val : g_boa;

        float acc[2][8][4];
#pragma unroll
        for (int i = 0; i < 2; i++)
#pragma unroll
            for (int j = 0; j < 8; j++)
#pragma unroll
                for (int k = 0; k < 4; k++) acc[i][j][k] = 0.f;

        auto loadChunk = [&](int c, int s) {
            uint32_t as = smem_u32(smem + s * BUF);
            uint32_t bs = as + O_B;
#pragma unroll
            for (int i = 0; i < 4; i++) {           // A: 1024 uint4
                int f = tid + 256 * i;
                int row = f >> 3, u = f & 7;
                uint32_t so = (row << 7) + (((u ^ (row & 7))) << 4);
                size_t gi = (size_t)(c * MTOT + mBase + row) * 8 + u;
                cp16(as + so, Ag + gi);
            }
#pragma unroll
            for (int i = 0; i < 4; i++) {           // B: 1024 uint4
                int f = tid + 256 * i;
                int n = f >> 3, u = f & 7;
                uint32_t so = (n << 7) + (((u ^ (n & 7))) << 4);
                size_t gi = (size_t)(c * N + nBase + n) * 8 + u;
                cp16(bs + so, Bg + gi);
            }
            asm volatile("cp.async.commit_group;" ::: "memory");
        };

        loadChunk(0, 0);
        loadChunk(1, 1);

        for (int c = 0; c < 4; c++) {
            if (c < 3) asm volatile("cp.async.wait_group 1;" ::: "memory");
            else       asm volatile("cp.async.wait_group 0;" ::: "memory");
            __syncthreads();
            if (c < 2) loadChunk(c + 2, (c + 2) % 3);

            const uint32_t As = smem_u32(smem + (c % 3) * BUF);
            const uint32_t Bs = As + O_B;

#pragma unroll
            for (int kk = 0; kk < 4; kk++) {
                uint32_t ah[2][4];
#pragma unroll
                for (int mi = 0; mi < 2; mi++) {
                    int r = warpM + mi * 16 + (lane & 15);
                    int u = kk * 2 + (lane >> 4);
                    uint32_t off = (r << 7) + (((u ^ (r & 7))) << 4);
                    ldsm4(ah[mi], As + off);
                }
                uint32_t bh[8][2];
#pragma unroll
                for (int p = 0; p < 4; p++) {
                    int r = warpN + p * 16 + ((lane >> 4) << 3) + (lane & 7);
                    int u = kk * 2 + ((lane >> 3) & 1);
                    uint32_t off = (r << 7) + (((u ^ (r & 7))) << 4);
                    ldsm4(&bh[p * 2][0], Bs + off);
                }
#pragma unroll
                for (int mi = 0; mi < 2; mi++)
#pragma unroll
                    for (int nj = 0; nj < 8; nj++)
                        mma16816(acc[mi][nj], ah[mi], bh[nj]);
            }
            if (c < 3) __syncthreads();
        }

#pragma unroll
        for (int mi = 0; mi < 2; mi++) {
            int row0 = mBase + warpM + mi * 16 + (lane >> 2);
#pragma unroll
            for (int nj = 0; nj < 8; nj++) {
                int col = nBase + warpN + nj * 8 + (lane & 3) * 2;
                float bx2 = __ldg(bias + col), by2 = __ldg(bias + col + 1);
                float v00 = acc[mi][nj][0] + bx2, v01 = acc[mi][nj][1] + by2;
                float v10 = acc[mi][nj][2] + bx2, v11 = acc[mi][nj][3] + by2;
                if (isVal) {
                    *(__half2*)(g_value_h + (size_t)row0 * 256 + col)       = __floats2half2_rn(v00, v01);
                    *(__half2*)(g_value_h + (size_t)(row0 + 8) * 256 + col) = __floats2half2_rn(v10, v11);
                } else {
                    *(float2*)(g_oa + (size_t)row0 * 384 + col)       = make_float2(v00, v01);
                    *(float2*)(g_oa + (size_t)(row0 + 8) * 384 + col) = make_float2(v10, v11);
                }
            }
        }
        __syncthreads();   // smem safe before next tile's prologue
    }
}

// ---------------------------------------------------------------------------
// Output GEMM, persistent grid-stride over 680 tiles (2 x 340).
// ---------------------------------------------------------------------------
__global__ __launch_bounds__(256, 2) void gemm_out(
    const float* __restrict__ bias, float* __restrict__ C)
{
    extern __shared__ char smem[];
    constexpr int BUF = 32768, O_B = 16384;
    constexpr int N = 256;

    const int tid  = threadIdx.x;
    const int wid  = tid >> 5;
    const int lane = tid & 31;
    const int warpM = (wid & 3) * 32;
    const int warpN = (wid >> 2) * 64;

    const uint4* Ag = (const uint4*)g_core_h;
    const uint4* Bg = (const uint4*)g_wu;

    for (int tile = blockIdx.x; tile < 2 * 340; tile += gridDim.x) {
        const int mBase = (tile % 340) * 128;
        const int nBase = (tile / 340) * 128;

        float acc[2][8][4];
#pragma unroll
        for (int i = 0; i < 2; i++)
#pragma unroll
            for (int j = 0; j < 8; j++)
#pragma unroll
                for (int k = 0; k < 4; k++) acc[i][j][k] = 0.f;

        auto loadChunk = [&](int c, int s) {
            uint32_t as = smem_u32(smem + s * BUF);
            uint32_t bs = as + O_B;
#pragma unroll
            for (int i = 0; i < 4; i++) {
                int f = tid + 256 * i;
                int row = f >> 3, u = f & 7;
                uint32_t so = (row << 7) + (((u ^ (row & 7))) << 4);
                size_t gi = (size_t)(c * MTOT + mBase + row) * 8 + u;
                cp16(as + so, Ag + gi);
            }
#pragma unroll
            for (int i = 0; i < 4; i++) {
                int f = tid + 256 * i;
                int n = f >> 3, u = f & 7;
                uint32_t so = (n << 7) + (((u ^ (n & 7))) << 4);
                size_t gi = (size_t)(c * N + nBase + n) * 8 + u;
                cp16(bs + so, Bg + gi);
            }
            asm volatile("cp.async.commit_group;" ::: "memory");
        };

        loadChunk(0, 0);
        loadChunk(1, 1);

        for (int c = 0; c < 4; c++) {
            if (c < 3) asm volatile("cp.async.wait_group 1;" ::: "memory");
            else       asm volatile("cp.async.wait_group 0;" ::: "memory");
            __syncthreads();
            if (c < 2) loadChunk(c + 2, (c + 2) % 3);

            const uint32_t As = smem_u32(smem + (c % 3) * BUF);
            const uint32_t Bs = As + O_B;

#pragma unroll
            for (int kk = 0; kk < 4; kk++) {
                uint32_t ah[2][4];
#pragma unroll
                for (int mi = 0; mi < 2; mi++) {
                    int r = warpM + mi * 16 + (lane & 15);
                    int u = kk * 2 + (lane >> 4);
                    uint32_t off = (r << 7) + (((u ^ (r & 7))) << 4);
                    ldsm4(ah[mi], As + off);
                }
                uint32_t bh[8][2];
#pragma unroll
                for (int p = 0; p < 4; p++) {
                    int r = warpN + p * 16 + ((lane >> 4) << 3) + (lane & 7);
                    int u = kk * 2 + ((lane >> 3) & 1);
                    uint32_t off = (r << 7) + (((u ^ (r & 7))) << 4);
                    ldsm4(&bh[p * 2][0], Bs + off);
                }
#pragma unroll
                for (int mi = 0; mi < 2; mi++)
#pragma unroll
                    for (int nj = 0; nj < 8; nj++)
                        mma16816(acc[mi][nj], ah[mi], bh[nj]);
            }
            if (c < 3) __syncthreads();
        }

#pragma unroll
        for (int mi = 0; mi < 2; mi++) {
            int row0 = mBase + warpM + mi * 16 + (lane >> 2);
#pragma unroll
            for (int nj = 0; nj < 8; nj++) {
                int col = nBase + warpN + nj * 8 + (lane & 3) * 2;
                float bx = __ldg(bias + col), by = __ldg(bias + col + 1);
                *(float2*)(C + (size_t)row0 * N + col) =
                    make_float2(acc[mi][nj][0] + bx, acc[mi][nj][1] + by);
                *(float2*)(C + (size_t)(row0 + 8) * N + col) =
                    make_float2(acc[mi][nj][2] + bx, acc[mi][nj][3] + by);
            }
        }
        __syncthreads();
    }
}

// ---------------------------------------------------------------------------
// Fused softmax + deformable sampling (R13 structure, half2 inner products).
// Block = 256 threads = 2 query rows x 8 heads = 16 head-slots.
// Phase 2: warp serves 2 head-slots, 16 lanes per slot, lane = 2 channels
// (half2). Corner products + 4-corner sum in fp16 (HMUL2/HFMA2), point sums
// accumulated in fp32. Weights stored packed fp16 in phase 1.
// ---------------------------------------------------------------------------
__global__ __launch_bounds__(256) void msda_sample(const float* __restrict__ refp)
{
    __shared__ int4  si [16][17];
    __shared__ uint2 swh[16][17];   // 4 fp16 weights per (slot, point)

    const int tid = threadIdx.x;
    const int rowBase = blockIdx.x * 2;

    // ---- Phase 1: per-(head,point) setup ----
    {
        const int hs  = tid >> 4;        // head slot 0..15
        const int s   = tid & 15;        // point (lvl*4 + pt)
        const int row = rowBase + (hs >> 3);
        const int h   = hs & 7;
        const int b   = row / LQ;

        const int lvl = s >> 2;
        const int Wl  = 64 >> lvl;
        const int st  = (16384 - (16384 >> (2 * lvl))) / 3;

        const float refx = refp[row * 8 + lvl * 2 + 0];
        const float refy = refp[row * 8 + lvl * 2 + 1];
        const int obase  = row * 384 + ((h * 16 + s) * 2);
        const float offx = g_oa[obase + 0];
        const float offy = g_oa[obase + 1];

        const float x = refx * (float)Wl + offx - 0.5f;
        const float y = refy * (float)Wl + offy - 0.5f;
        const float fx = floorf(x), fy = floorf(y);
        const float lx = x - fx,   ly = y - fy;
        const int x0 = (int)fx, y0 = (int)fy;
        const int x1 = x0 + 1,  y1 = y0 + 1;

        const float logit = g_oa[row * 384 + 256 + h * 16 + s];
        float mx = logit;
#pragma unroll
        for (int o = 8; o; o >>= 1) mx = fmaxf(mx, __shfl_xor_sync(~0u, mx, o, 16));
        const float e = __expf(logit - mx);
        float sum = e;
#pragma unroll
        for (int o = 8; o; o >>= 1) sum += __shfl_xor_sync(~0u, sum, o, 16);
        const float wa = e / sum;

        const bool vx0 = (unsigned)x0 < (unsigned)Wl;
        const bool vx1 = (unsigned)x1 < (unsigned)Wl;
        const bool vy0 = (unsigned)y0 < (unsigned)Wl;
        const bool vy1 = (unsigned)y1 < (unsigned)Wl;
        const int cx0 = min(max(x0, 0), Wl - 1);
        const int cx1 = min(max(x1, 0), Wl - 1);
        const int cy0 = min(max(y0, 0), Wl - 1);
        const int cy1 = min(max(y1, 0), Wl - 1);
        const int rb  = b * LIN + st;

        si[hs][s] = make_int4(rb + cy0 * Wl + cx0, rb + cy0 * Wl + cx1,
                              rb + cy1 * Wl + cx0, rb + cy1 * Wl + cx1);
        const float w00 = wa * (1.f - lx) * (1.f - ly) * (float)(vx0 && vy0);
        const float w01 = wa * lx         * (1.f - ly) * (float)(vx1 && vy0);
        const float w10 = wa * (1.f - lx) * ly         * (float)(vx0 && vy1);
        const float w11 = wa * lx         * ly         * (float)(vx1 && vy1);
        __half2 wA = __floats2half2_rn(w00, w01);
        __half2 wB = __floats2half2_rn(w10, w11);
        uint2 pk;
        pk.x = *(uint32_t*)&wA;
        pk.y = *(uint32_t*)&wB;
        swh[hs][s] = pk;
    }
    __syncthreads();

    // ---- Phase 2: gather + accumulate (fp16 products, fp32 point sums) ----
    const int wid  = tid >> 5;
    const int lane = tid & 31;
    const int hs   = wid * 2 + (lane >> 4);
    const int row  = rowBase + (hs >> 3);
    const int h    = hs & 7;
    const int c2   = (lane & 15) * 2;          // channel pair

    const __half* __restrict__ vp = g_value_h + h * 32 + c2;
    float ax = 0.f, ay = 0.f;
#pragma unroll 4
    for (int t = 0; t < 16; t++) {
        const int4  id = si[hs][t];
        const uint2 wp = swh[hs][t];
        const __half2 wA = *(const __half2*)&wp.x;   // (w00, w01)
        const __half2 wB = *(const __half2*)&wp.y;   // (w10, w11)
        const __half2 f0 = *(const __half2*)(vp + (size_t)id.x * 256);
        const __half2 f1 = *(const __half2*)(vp + (size_t)id.y * 256);
        const __half2 f2 = *(const __half2*)(vp + (size_t)id.z * 256);
        const __half2 f3 = *(const __half2*)(vp + (size_t)id.w * 256);
        __half2 p = __hmul2(f0, __half2half2(__low2half(wA)));
        p = __hfma2(f1, __half2half2(__high2half(wA)), p);
        p = __hfma2(f2, __half2half2(__low2half(wB)),  p);
        p = __hfma2(f3, __half2half2(__high2half(wB)), p);
        const float2 pf = __half22float2(p);
        ax += pf.x;
        ay += pf.y;
    }

    // single fp16 core in out-GEMM chunk layout (k = h*32 + c2)
    size_t o = ((size_t)(h >> 1) * MTOT + row) * 64 + (h & 1) * 32 + c2;
    *(__half2*)(g_core_h + o) = __floats2half2_rn(ax, ay);
}

// ---------------------------------------------------------------------------
extern "C" void kernel_launch(void* const* d_in, const int* in_sizes, int n_in,
                              void* d_out, int out_size)
{
    const float* query  = (const float*)d_in[0];
    const float* refp   = (const float*)d_in[1];
    const float* inpf   = (const float*)d_in[2];
    const float* W_val  = (const float*)d_in[5];
    const float* b_val  = (const float*)d_in[6];
    const float* W_off  = (const float*)d_in[7];
    const float* b_off  = (const float*)d_in[8];
    const float* W_attn = (const float*)d_in[9];
    const float* b_attn = (const float*)d_in[10];
    const float* W_out  = (const float*)d_in[11];
    const float* b_out  = (const float*)d_in[12];
    float* out = (float*)d_out;

    constexpr int SMEM = 98304;   // 3 x 32KB
    cudaFuncSetAttribute(gemm_dual, cudaFuncAttributeMaxDynamicSharedMemorySize, SMEM);
    cudaFuncSetAttribute(gemm_out,  cudaFuncAttributeMaxDynamicSharedMemorySize, SMEM);

    prep_convert<<<896 + 10880, 256>>>(W_val, W_off, W_attn, W_out,
                                       b_off, b_attn, inpf, query);

    gemm_dual<<<296, 256, SMEM>>>(b_val);   // persistent: 1700 tiles

    msda_sample<<<MTOT / 2, 256>>>(refp);

    gemm_out<<<296, 256, SMEM>>>(b_out, out);  // persistent: 680 tiles
}